// round 1
// baseline (speedup 1.0000x reference)
#include <cuda_runtime.h>
#include <math.h>

// Problem constants
#define DD 256          // feature dim
#define PP 64           // num patterns
#define SS 1024         // seq len
#define NROWS 65536LL   // b*h*s = 4*16*1024
#define TINV 10.0f      // 1/temperature

// Output region offsets (floats), in reference return order:
// routing_scores (4,16,1024) | optimal_routes (4,16,1024,1024) | transfer_weights (16,64,64) | pattern_scores (4,16,1024,64)
#define OFF_ROUTING 0LL
#define N_ROUTING   65536LL
#define OFF_ROUTES  65536LL
#define N_ROUTES    67108864LL
#define OFF_TW      67174400LL
#define N_TW        65536LL
#define OFF_PS      67239936LL

// Normalized patterns, transposed: g_patT[k*64 + p]
__device__ float g_patT[DD * PP];

// ---------------------------------------------------------------------------
// Kernel 1: normalize patterns (tiny: 64 rows of 256)
// ---------------------------------------------------------------------------
__global__ void normalize_patterns_kernel(const float* __restrict__ patterns) {
    int p = threadIdx.x;
    if (p >= PP) return;
    float ss = 0.0f;
    #pragma unroll 8
    for (int k = 0; k < DD; k++) {
        float v = patterns[p * DD + k];
        ss = fmaf(v, v, ss);
    }
    float n = sqrtf(ss);
    float inv = 1.0f / fmaxf(n, 1e-12f);
    for (int k = 0; k < DD; k++) {
        g_patT[k * PP + p] = patterns[p * DD + k] * inv;
    }
}

// ---------------------------------------------------------------------------
// Kernel 2: routing_scores fill (= 1/1024 exactly) + transfer_weights copy
// ---------------------------------------------------------------------------
__global__ void small_fill_kernel(float* __restrict__ routing,
                                  float* __restrict__ tw_out,
                                  const float* __restrict__ tw_in) {
    int i = blockIdx.x * blockDim.x + threadIdx.x;   // 65536 threads
    routing[i] = 1.0f / 1024.0f;
    tw_out[i]  = tw_in[i];
}

// ---------------------------------------------------------------------------
// Kernel 3: optimal_routes fill. Value depends only on last-dim index j:
//   v[j] = -(float)j / 1024   (exact match to the reference scan in fp32)
// 16777216 float4 streaming stores.
// ---------------------------------------------------------------------------
__global__ void fill_routes_kernel(float4* __restrict__ out4) {
    long long q = (long long)blockIdx.x * blockDim.x + threadIdx.x;
    int c = (int)((q << 2) & 1023);
    const float r = 1.0f / 1024.0f;
    float4 v;
    v.x = -(float)(c + 0) * r;
    v.y = -(float)(c + 1) * r;
    v.z = -(float)(c + 2) * r;
    v.w = -(float)(c + 3) * r;
    __stcs(&out4[q], v);   // streaming: don't pollute L2 (patterns/states live there)
}

// ---------------------------------------------------------------------------
// Kernel 4: pattern_scores = softmax( (states @ patN^T) * 10, axis=p )
// Tiled fp32 GEMM: 64-row tile x 64 patterns, K=256 in chunks of 64.
// Thread tile 4 rows x 4 patterns (16 accumulators), 256 threads (16x16).
// smem: sB = full normalized-pattern matrix [256][64] (64 KB),
//       sA = A chunk [64 rows][68 pitch] (17 KB), aliased as score tile in epilogue.
// ---------------------------------------------------------------------------
#define KCHUNK 64
#define PITCHA 68
#define TR 64
#define GEMM_SMEM_BYTES ((DD * PP + TR * PITCHA) * 4)

__global__ __launch_bounds__(256, 2)
void pattern_scores_kernel(const float* __restrict__ states,
                           float* __restrict__ outps) {
    extern __shared__ float smem[];
    float* sB = smem;            // [256][64]
    float* sA = smem + DD * PP;  // [64][PITCHA]

    int tid = threadIdx.x;

    // Stage full normalized-pattern matrix
    for (int i = tid; i < DD * PP; i += 256) sB[i] = g_patT[i];

    long long rowBase = (long long)blockIdx.x * TR;
    const float* A = states + rowBase * DD;

    int tx = tid & 15;    // pattern group: patterns tx*4 .. tx*4+3
    int ty = tid >> 4;    // row group:     rows     ty*4 .. ty*4+3

    float acc[4][4];
    #pragma unroll
    for (int r = 0; r < 4; r++)
        #pragma unroll
        for (int p = 0; p < 4; p++) acc[r][p] = 0.0f;

    for (int k0 = 0; k0 < DD; k0 += KCHUNK) {
        __syncthreads();  // also covers sB visibility on first pass
        // Load A chunk: 64 rows x 64 k (float4 coalesced), row-major with pad
        for (int i = tid; i < TR * KCHUNK / 4; i += 256) {
            int row = i >> 4;
            int kq  = (i & 15) << 2;
            float4 v = *(const float4*)&A[(long long)row * DD + k0 + kq];
            float* dst = &sA[row * PITCHA + kq];
            dst[0] = v.x; dst[1] = v.y; dst[2] = v.z; dst[3] = v.w;
        }
        __syncthreads();

        #pragma unroll 8
        for (int k = 0; k < KCHUNK; k++) {
            const float* bp = &sB[(k0 + k) * PP + tx * 4];
            float b0 = bp[0], b1 = bp[1], b2 = bp[2], b3 = bp[3];
            #pragma unroll
            for (int r = 0; r < 4; r++) {
                float a = sA[(ty * 4 + r) * PITCHA + k];   // broadcast across tx
                acc[r][0] = fmaf(a, b0, acc[r][0]);
                acc[r][1] = fmaf(a, b1, acc[r][1]);
                acc[r][2] = fmaf(a, b2, acc[r][2]);
                acc[r][3] = fmaf(a, b3, acc[r][3]);
            }
        }
    }
    __syncthreads();

    // Epilogue: softmax over the 64 patterns per row. Reuse sA as [64][65].
    float* sScore = sA;
    #pragma unroll
    for (int r = 0; r < 4; r++)
        #pragma unroll
        for (int p = 0; p < 4; p++)
            sScore[(ty * 4 + r) * 65 + tx * 4 + p] = acc[r][p];
    __syncthreads();

    if (tid < TR) {
        float* rowp = &sScore[tid * 65];
        float mx = -1e30f;
        #pragma unroll
        for (int p = 0; p < PP; p++) mx = fmaxf(mx, rowp[p]);
        mx *= TINV;
        float sum = 0.0f;
        #pragma unroll
        for (int p = 0; p < PP; p++) {
            float e = expf(rowp[p] * TINV - mx);
            rowp[p] = e;
            sum += e;
        }
        float inv = 1.0f / sum;
        #pragma unroll
        for (int p = 0; p < PP; p++) rowp[p] *= inv;
    }
    __syncthreads();

    // Coalesced float4 store of the 64x64 tile
    float* O = outps + rowBase * PP;
    for (int i = tid; i < TR * PP / 4; i += 256) {
        int row = i >> 4;
        int pq  = (i & 15) << 2;
        float4 v = make_float4(sScore[row * 65 + pq + 0],
                               sScore[row * 65 + pq + 1],
                               sScore[row * 65 + pq + 2],
                               sScore[row * 65 + pq + 3]);
        *(float4*)&O[row * PP + pq] = v;
    }
}

// ---------------------------------------------------------------------------
// Launch
// ---------------------------------------------------------------------------
extern "C" void kernel_launch(void* const* d_in, const int* in_sizes, int n_in,
                              void* d_out, int out_size) {
    const float* states   = (const float*)d_in[0];  // (4,16,1024,256)
    const float* patterns = (const float*)d_in[1];  // (64,256)
    const float* tw       = (const float*)d_in[2];  // (16,64,64) zeros
    float* out = (float*)d_out;

    cudaFuncSetAttribute(pattern_scores_kernel,
                         cudaFuncAttributeMaxDynamicSharedMemorySize,
                         GEMM_SMEM_BYTES);

    normalize_patterns_kernel<<<1, 64>>>(patterns);

    small_fill_kernel<<<256, 256>>>(out + OFF_ROUTING, out + OFF_TW, tw);

    // 67108864 floats / 4 per thread / 256 per block = 65536 blocks
    fill_routes_kernel<<<65536, 256>>>((float4*)(out + OFF_ROUTES));

    pattern_scores_kernel<<<1024, 256, GEMM_SMEM_BYTES>>>(states, out + OFF_PS);
}

// round 2
// speedup vs baseline: 1.3960x; 1.3960x over previous
#include <cuda_runtime.h>
#include <math.h>

typedef unsigned long long ull;

// Problem constants
#define DD 256
#define PP 64
#define SS 1024
#define TINV 10.0f

// Output offsets (floats): routing(65536) | routes(67108864) | tw(65536) | ps(4194304)
#define OFF_ROUTING 0LL
#define OFF_ROUTES  65536LL
#define OFF_TW      67174400LL
#define OFF_PS      67239936LL

// Grid layout of fused kernel:
//  - 512 GEMM blocks (M-tile 128), spread at every 17th bid over [0, 8704)
//  - 8192 route-fill blocks (2048 float4 each)
//  - 64 small-fill blocks (routing + tw)
#define N_GEMM 512
#define GRID_TOTAL 8768

// smem: sAT [64][130] (33280 B) then sB [64][68] (17408 B)
#define PITCH_A 130
#define PITCH_B 68
#define KC 64
#define SMEM_FLOATS (KC * PITCH_A + KC * PITCH_B)
#define SMEM_BYTES  (SMEM_FLOATS * 4)

// Normalized patterns, k-major: g_patT[k*64 + p]
__device__ float g_patT[DD * PP];

__global__ void normalize_patterns_kernel(const float* __restrict__ patterns) {
    int p = threadIdx.x;
    if (p >= PP) return;
    float ss = 0.0f;
    #pragma unroll 8
    for (int k = 0; k < DD; k++) {
        float v = patterns[p * DD + k];
        ss = fmaf(v, v, ss);
    }
    float inv = 1.0f / fmaxf(sqrtf(ss), 1e-12f);
    for (int k = 0; k < DD; k++)
        g_patT[k * PP + p] = patterns[p * DD + k] * inv;
}

// ---- packed fp32 helpers (FFMA2 path; ptxas won't auto-fuse) ----
__device__ __forceinline__ void fma2(ull& d, ull a, ull b) {
    asm("fma.rn.f32x2 %0, %1, %2, %3;" : "=l"(d) : "l"(a), "l"(b), "l"(d));
}
__device__ __forceinline__ ull splat2(float x) {
    ull r; unsigned int u = __float_as_uint(x);
    asm("mov.b64 %0, {%1, %1};" : "=l"(r) : "r"(u));
    return r;
}
__device__ __forceinline__ void unpack2(ull v, float& lo, float& hi) {
    unsigned int l, h;
    asm("mov.b64 {%0, %1}, %2;" : "=r"(l), "=r"(h) : "l"(v));
    lo = __uint_as_float(l); hi = __uint_as_float(h);
}

// ---------------------------------------------------------------------------
// Fused kernel: GEMM+softmax tiles, routes fill, small fills — one launch so
// DRAM-bound fill CTAs overlap FMA-bound GEMM CTAs on every SM.
// ---------------------------------------------------------------------------
__global__ __launch_bounds__(256, 3)
void fused_kernel(const float* __restrict__ states,
                  const float* __restrict__ tw_in,
                  float* __restrict__ out) {
    extern __shared__ float smem[];
    int bid = blockIdx.x;
    int tid = threadIdx.x;

    bool isGemm = (bid < 17 * N_GEMM) && (bid % 17 == 0);

    if (!isGemm) {
        long long fillIdx = (bid < 17 * N_GEMM) ? (bid - (bid + 16) / 17)
                                                : (bid - N_GEMM);
        if (fillIdx < 8192) {
            // optimal_routes: value depends only on column j: -(float)j/1024
            float4* out4 = (float4*)(out + OFF_ROUTES);
            long long base = fillIdx * 2048;
            const float r = 1.0f / 1024.0f;
            #pragma unroll
            for (int it = 0; it < 8; it++) {
                long long q = base + it * 256 + tid;
                int c = (int)(q & 255) << 2;
                float4 v;
                v.x = -(float)(c + 0) * r;
                v.y = -(float)(c + 1) * r;
                v.z = -(float)(c + 2) * r;
                v.w = -(float)(c + 3) * r;
                __stcs(&out4[q], v);
            }
        } else {
            // routing_scores = 1/1024 exactly; transfer_weights passthrough
            int i4 = (int)(fillIdx - 8192) * 256 + tid;   // 16384 float4 each
            const float r = 1.0f / 1024.0f;
            ((float4*)(out + OFF_ROUTING))[i4] = make_float4(r, r, r, r);
            ((float4*)(out + OFF_TW))[i4] = ((const float4*)tw_in)[i4];
        }
        return;
    }

    // ---------------- GEMM + softmax tile ----------------
    int gemmIdx = bid / 17;
    long long rowBase = (long long)gemmIdx * 128;
    const float* A = states + rowBase * DD;

    float* sAT = smem;                  // [KC][PITCH_A]  k-major A chunk
    float* sB  = smem + KC * PITCH_A;   // [KC][PITCH_B]

    int tx = tid & 15;   // pattern group: tx*4 .. tx*4+3
    int ty = tid >> 4;   // row group:     ty*8 .. ty*8+7 (4 packed pairs)

    ull acc[4][4];
    #pragma unroll
    for (int q = 0; q < 4; q++)
        #pragma unroll
        for (int p = 0; p < 4; p++) acc[q][p] = 0ULL;

    for (int k0 = 0; k0 < DD; k0 += KC) {
        __syncthreads();
        // B chunk: [KC][64] float4-coalesced
        for (int i = tid; i < KC * PP / 4; i += 256) {
            int kl = i >> 4, pq = (i & 15) << 2;
            float4 v = *(const float4*)&g_patT[(k0 + kl) * PP + pq];
            *(float4*)&sB[kl * PITCH_B + pq] = v;
        }
        // A chunk transposed: sAT[k][row] so row-pairs load as LDS.64
        for (int i = tid; i < 128 * KC / 4; i += 256) {
            int row = i >> 4, kq = (i & 15) << 2;
            float4 v = *(const float4*)&A[(long long)row * DD + k0 + kq];
            sAT[(kq + 0) * PITCH_A + row] = v.x;
            sAT[(kq + 1) * PITCH_A + row] = v.y;
            sAT[(kq + 2) * PITCH_A + row] = v.z;
            sAT[(kq + 3) * PITCH_A + row] = v.w;
        }
        __syncthreads();

        #pragma unroll 8
        for (int k = 0; k < KC; k++) {
            const float* ap = &sAT[k * PITCH_A + ty * 8];
            ull a0 = *(const ull*)(ap + 0);
            ull a1 = *(const ull*)(ap + 2);
            ull a2 = *(const ull*)(ap + 4);
            ull a3 = *(const ull*)(ap + 6);
            float4 bv = *(const float4*)&sB[k * PITCH_B + tx * 4];
            ull B0 = splat2(bv.x), B1 = splat2(bv.y);
            ull B2 = splat2(bv.z), B3 = splat2(bv.w);
            fma2(acc[0][0], a0, B0); fma2(acc[0][1], a0, B1);
            fma2(acc[0][2], a0, B2); fma2(acc[0][3], a0, B3);
            fma2(acc[1][0], a1, B0); fma2(acc[1][1], a1, B1);
            fma2(acc[1][2], a1, B2); fma2(acc[1][3], a1, B3);
            fma2(acc[2][0], a2, B0); fma2(acc[2][1], a2, B1);
            fma2(acc[2][2], a2, B2); fma2(acc[2][3], a2, B3);
            fma2(acc[3][0], a3, B0); fma2(acc[3][1], a3, B1);
            fma2(acc[3][2], a3, B2); fma2(acc[3][3], a3, B3);
        }
    }
    __syncthreads();

    // Epilogue: scores into smem [128][65] (fits in sAT region: 8320 floats)
    float* sS = smem;
    #pragma unroll
    for (int q = 0; q < 4; q++)
        #pragma unroll
        for (int p = 0; p < 4; p++) {
            float lo, hi;
            unpack2(acc[q][p], lo, hi);
            sS[(ty * 8 + 2 * q + 0) * 65 + tx * 4 + p] = lo;
            sS[(ty * 8 + 2 * q + 1) * 65 + tx * 4 + p] = hi;
        }
    __syncthreads();

    if (tid < 128) {
        float* rowp = &sS[tid * 65];
        float mx = -1e30f;
        #pragma unroll
        for (int p = 0; p < PP; p++) mx = fmaxf(mx, rowp[p]);
        mx *= TINV;
        float sum = 0.0f;
        #pragma unroll
        for (int p = 0; p < PP; p++) {
            float e = __expf(rowp[p] * TINV - mx);
            rowp[p] = e;
            sum += e;
        }
        float inv = 1.0f / sum;
        #pragma unroll
        for (int p = 0; p < PP; p++) rowp[p] *= inv;
    }
    __syncthreads();

    float* O = out + OFF_PS + rowBase * PP;
    for (int i = tid; i < 128 * PP / 4; i += 256) {
        int row = i >> 4, pq = (i & 15) << 2;
        float4 v = make_float4(sS[row * 65 + pq + 0],
                               sS[row * 65 + pq + 1],
                               sS[row * 65 + pq + 2],
                               sS[row * 65 + pq + 3]);
        *(float4*)&O[row * PP + pq] = v;
    }
}

extern "C" void kernel_launch(void* const* d_in, const int* in_sizes, int n_in,
                              void* d_out, int out_size) {
    const float* states   = (const float*)d_in[0];  // (4,16,1024,256)
    const float* patterns = (const float*)d_in[1];  // (64,256)
    const float* tw       = (const float*)d_in[2];  // (16,64,64)
    float* out = (float*)d_out;

    cudaFuncSetAttribute(fused_kernel,
                         cudaFuncAttributeMaxDynamicSharedMemorySize,
                         SMEM_BYTES);

    normalize_patterns_kernel<<<1, 64>>>(patterns);
    fused_kernel<<<GRID_TOTAL, 256, SMEM_BYTES>>>(states, tw, out);
}